// round 10
// baseline (speedup 1.0000x reference)
#include <cuda_runtime.h>
#include <cstdint>

// ---------------- problem constants ----------------
#define B      128
#define D      768
#define POOL   100
#define LG     6
#define LE     6
#define GLEN   5
#define ELEN   20
#define H      12
#define HD     64
#define TOPK   5

// Output rows: one row = HD floats = 16 float4 = 256 bytes.
#define G_ROWS     (LG*2*B*H*GLEN)              // 92,160
#define E_ROWS     (LE*2*B*H*(TOPK*ELEN))       // 1,843,200
#define G_PAIRS    (G_ROWS*8)                   // 737,280
#define E_PAIRS    (E_ROWS*8)                   // 14,745,600

#define THREADS    256
#define SEL_BLOCKS 128
#define G_BLOCKS   (G_PAIRS/THREADS)            // 2,880 (exact)
#define E_BLOCKS   (E_PAIRS/THREADS)            // 57,600 (exact)
#define TOTAL_BLOCKS (SEL_BLOCKS + G_BLOCKS + E_BLOCKS)   // 60,608

// scratch (no cudaMalloc allowed)
__device__ int d_idx[B * TOPK];
__device__ int d_flag;            // reset to 0 via cudaMemsetAsync each call

// ---------------------------------------------------------------------------
// Single fused kernel, register-capped (<=32 regs, 8 blocks/SM).
//  blocks [0,128):          selection (wave-1 resident; fence+atomic publish)
//  blocks [128,128+2880):   g-region writer (independent)
//  blocks [128+2880,...):   e-region writer.
// KEY CHANGE vs R7/R9: the e-branch dependency check is a BARRIER-FREE
// per-thread poll (broadcast ld.cg, one L2 req per warp, nanosleep backoff).
// No thread-0 spin, no __syncthreads: at block start every warp proceeds
// straight into its load stream, preserving R4's cross-block load pipelining.
// In steady state the poll is a single extra L2-latency link on the d_idx
// chain, fully hidden by 64-warp/SM pipelining.
// ---------------------------------------------------------------------------
__global__ __launch_bounds__(THREADS, 8) void dual_prompt_kernel(
        const float4* __restrict__ query4,
        const float4* __restrict__ keys4,
        const float4* __restrict__ g4,
        const float4* __restrict__ pool4,
        float4* __restrict__ out4) {
    const int blk = blockIdx.x;

    if (blk >= SEL_BLOCKS + G_BLOCKS) {
        // ===== e region: out[ld,b,h,m,:] = pool[idx[b][m/ELEN], ld, m%ELEN, h, :]
        int gid = (blk - SEL_BLOCKS - G_BLOCKS) * THREADS + threadIdx.x; // < E_PAIRS exact
        const int c4h = gid & 7;
        const int row = gid >> 3;              // 0..E_ROWS-1

        // index math BEFORE the poll — overlaps with the flag load
        int v  = row;
        int m  = v % (TOPK * ELEN); v /= (TOPK * ELEN);
        int h  = v % H;             v /= H;
        int b  = v & 127;           v >>= 7;
        int ld = v;                            // 0..11
        int k  = m / ELEN;
        int e  = m - k * ELEN;

        // barrier-free per-thread poll (broadcast within warp; normally 1 iter)
        int f;
        asm volatile("ld.global.cg.b32 %0, [%1];" : "=r"(f) : "l"(&d_flag));
        while (f < SEL_BLOCKS) {
            __nanosleep(200);
            asm volatile("ld.global.cg.b32 %0, [%1];" : "=r"(f) : "l"(&d_flag));
        }

        int p  = __ldcg(&d_idx[b * TOPK + k]);  // L2-coherent; control-dep on flag

        const float4* src = &pool4[((((p * 12 + ld) * ELEN + e) * H + h) << 4) + c4h];
        float4 v0 = __ldg(src);
        float4 v1 = __ldg(src + 8);

        float4* dst = out4 + (((long long)G_ROWS + row) << 4) + c4h;
        __stcs(dst,     v0);
        __stcs(dst + 8, v1);
    } else if (blk >= SEL_BLOCKS) {
        // ===== g region: out[ld,b,h,gl,:] = g_prompt[ld,gl,h,:] =====
        int gid = (blk - SEL_BLOCKS) * THREADS + threadIdx.x;   // < G_PAIRS exact
        const int c4h = gid & 7;
        const int row = gid >> 3;
        int v  = row;
        int gl = v % GLEN; v /= GLEN;
        int h  = v % H;    v /= H;
        v >>= 7;                               // drop b
        int ld = v;                            // 0..11
        const float4* src = &g4[(((ld * GLEN + gl) * H + h) << 4) + c4h];
        float4 v0 = __ldg(src);
        float4 v1 = __ldg(src + 8);
        float4* dst = out4 + ((long long)row << 4) + c4h;
        __stcs(dst,     v0);
        __stcs(dst + 8, v1);
    } else {
        // ===== selection: one query row per block, 8 warps =====
        const int b    = blk;
        const int t    = threadIdx.x;
        const int warp = t >> 5;
        const int lane = t & 31;

        __shared__ float sims[POOL];

        const float4* qr = query4 + (size_t)b * (D / 4);
        float4 fq[6];
        #pragma unroll
        for (int j = 0; j < 6; j++) fq[j] = __ldg(&qr[lane + 32 * j]);

        // qn dropped: positive per-row constant, ranking-invariant.
        for (int p = warp; p < POOL; p += 8) {
            const float4* kr = keys4 + (size_t)p * (D / 4);
            float dot = 0.f, kk = 0.f;
            #pragma unroll
            for (int j = 0; j < 6; j++) {
                float4 kv = __ldg(&kr[lane + 32 * j]);
                dot = fmaf(fq[j].x, kv.x, dot);
                dot = fmaf(fq[j].y, kv.y, dot);
                dot = fmaf(fq[j].z, kv.z, dot);
                dot = fmaf(fq[j].w, kv.w, dot);
                kk  = fmaf(kv.x, kv.x, kk);
                kk  = fmaf(kv.y, kv.y, kk);
                kk  = fmaf(kv.z, kv.z, kk);
                kk  = fmaf(kv.w, kv.w, kk);
            }
            #pragma unroll
            for (int o = 16; o > 0; o >>= 1) {
                dot += __shfl_xor_sync(0xFFFFFFFFu, dot, o);
                kk  += __shfl_xor_sync(0xFFFFFFFFu, kk,  o);
            }
            if (lane == 0) {
                float kn = fmaxf(sqrtf(kk), 1e-12f);
                sims[p] = dot / kn;
            }
        }
        __syncthreads();

        // warp 0: parallel top-5 argmax, tie-break = lowest index (jax order)
        if (warp == 0) {
            #pragma unroll
            for (int k = 0; k < TOPK; k++) {
                float best = -3.0e38f;
                int   bi   = POOL;
                #pragma unroll
                for (int j = 0; j < 4; j++) {
                    int p = lane + 32 * j;
                    if (p < POOL) {
                        float v = sims[p];
                        if (v > best) { best = v; bi = p; }
                    }
                }
                #pragma unroll
                for (int o = 16; o > 0; o >>= 1) {
                    float ov = __shfl_xor_sync(0xFFFFFFFFu, best, o);
                    int   oi = __shfl_xor_sync(0xFFFFFFFFu, bi,   o);
                    if (ov > best || (ov == best && oi < bi)) { best = ov; bi = oi; }
                }
                if (lane == 0) {
                    d_idx[b * TOPK + k] = bi;
                    sims[bi] = -3.0e38f;
                }
                __syncwarp();
            }
            if (lane == 0) {
                __threadfence();               // publish d_idx before flag
                atomicAdd(&d_flag, 1);         // only 128 of these total
            }
        }
    }
}

// ---------------------------------------------------------------------------
extern "C" void kernel_launch(void* const* d_in, const int* in_sizes, int n_in,
                              void* d_out, int out_size) {
    const float* query = (const float*)d_in[0];
    const float* gprm  = (const float*)d_in[1];
    const float* pool  = (const float*)d_in[2];
    const float* keys  = (const float*)d_in[3];
    float* out = (float*)d_out;

    // reset in-kernel dependency flag (graph-capturable memset node)
    void* flag_addr = nullptr;
    cudaGetSymbolAddress(&flag_addr, d_flag);
    cudaMemsetAsync(flag_addr, 0, sizeof(int));

    dual_prompt_kernel<<<TOTAL_BLOCKS, THREADS>>>(
        (const float4*)query, (const float4*)keys,
        (const float4*)gprm, (const float4*)pool, (float4*)out);
}

// round 11
// speedup vs baseline: 2.0269x; 2.0269x over previous
#include <cuda_runtime.h>
#include <cstdint>

// ---------------- problem constants ----------------
#define B      128
#define D      768
#define POOL   100
#define LG     6
#define LE     6
#define GLEN   5
#define ELEN   20
#define H      12
#define HD     64
#define TOPK   5

// Output rows: one row = HD floats = 16 float4 = 256 bytes.
#define G_ROWS     (LG*2*B*H*GLEN)              // 92,160
#define E_ROWS     (LE*2*B*H*(TOPK*ELEN))       // 1,843,200
#define TOTAL_ROWS (G_ROWS + E_ROWS)            // 1,935,360
#define TOTAL_PAIRS (TOTAL_ROWS * 8)            // 15,482,880

// scratch for selected indices (no cudaMalloc allowed)
__device__ int d_idx[B * TOPK];

// ---------------------------------------------------------------------------
// Kernel 1 (PDL primary): cosine-sim + top-5 selection.
// One block per query row: 512 threads = 16 warps; warp-per-dot-product with
// float4 coalesced loads; qn dropped (positive per-row constant => ranking
// invariant); warp-parallel argmax with lowest-index tie-break (jax order).
// Each block triggers programmatic launch completion after its d_idx row is
// published, letting the writer's dependent blocks proceed ASAP.
// ---------------------------------------------------------------------------
__global__ __launch_bounds__(512) void select_topk_kernel(
        const float4* __restrict__ query4,
        const float4* __restrict__ keys4) {
    const int b    = blockIdx.x;
    const int t    = threadIdx.x;
    const int warp = t >> 5;
    const int lane = t & 31;

    __shared__ float sims[POOL];

    const float4* qr = query4 + (size_t)b * (D / 4);
    float4 fq[6];
    #pragma unroll
    for (int j = 0; j < 6; j++) fq[j] = __ldg(&qr[lane + 32 * j]);

    for (int p = warp; p < POOL; p += 16) {
        const float4* kr = keys4 + (size_t)p * (D / 4);
        float dot = 0.f, kk = 0.f;
        #pragma unroll
        for (int j = 0; j < 6; j++) {
            float4 kv = __ldg(&kr[lane + 32 * j]);
            dot = fmaf(fq[j].x, kv.x, dot);
            dot = fmaf(fq[j].y, kv.y, dot);
            dot = fmaf(fq[j].z, kv.z, dot);
            dot = fmaf(fq[j].w, kv.w, dot);
            kk  = fmaf(kv.x, kv.x, kk);
            kk  = fmaf(kv.y, kv.y, kk);
            kk  = fmaf(kv.z, kv.z, kk);
            kk  = fmaf(kv.w, kv.w, kk);
        }
        #pragma unroll
        for (int o = 16; o > 0; o >>= 1) {
            dot += __shfl_xor_sync(0xFFFFFFFFu, dot, o);
            kk  += __shfl_xor_sync(0xFFFFFFFFu, kk,  o);
        }
        if (lane == 0) {
            float kn = fmaxf(sqrtf(kk), 1e-12f);
            sims[p] = dot / kn;
        }
    }
    __syncthreads();

    if (warp == 0) {
        #pragma unroll
        for (int k = 0; k < TOPK; k++) {
            float best = -3.0e38f;
            int   bi   = POOL;
            #pragma unroll
            for (int j = 0; j < 4; j++) {
                int p = lane + 32 * j;
                if (p < POOL) {
                    float v = sims[p];
                    if (v > best) { best = v; bi = p; }
                }
            }
            #pragma unroll
            for (int o = 16; o > 0; o >>= 1) {
                float ov = __shfl_xor_sync(0xFFFFFFFFu, best, o);
                int   oi = __shfl_xor_sync(0xFFFFFFFFu, bi,   o);
                if (ov > best || (ov == best && oi < bi)) { best = ov; bi = oi; }
            }
            if (lane == 0) {
                d_idx[b * TOPK + k] = bi;
                sims[bi] = -3.0e38f;
            }
            __syncwarp();
        }
    }
    __syncthreads();
    // This block's d_idx row is published -> allow dependent grid to proceed.
    cudaTriggerProgrammaticLaunchCompletion();
}

// ---------------------------------------------------------------------------
// Kernel 2 (PDL secondary): fused output writer — byte-identical memory
// pattern to R4's proven 83.7us version. One thread = one (row, half-slot):
// 2 float4 at columns c4h and c4h+8 of a 256B row; every LDG/STG covers
// exactly 4 full 128B lines. g-branch has NO dependency and runs overlapped
// with the primary; e-branch waits on the HW grid dependency (cheap,
// already-satisfied for all blocks beyond wave 1).
//   g region: out[ld,b,h,gl,:] = g_prompt[ld,gl,h,:]
//   e region: out[ld,b,h,m,:]  = pool[idx[b][m/ELEN], ld, m%ELEN, h, :]
// ---------------------------------------------------------------------------
__global__ __launch_bounds__(256) void write_out_kernel(
        const float4* __restrict__ g4,
        const float4* __restrict__ pool4,
        float4* __restrict__ out4) {
    int gid = blockIdx.x * blockDim.x + threadIdx.x;
    if (gid >= TOTAL_PAIRS) return;

    const int c4h = gid & 7;       // half-slot 0..7
    const int row = gid >> 3;      // output row (256B granule)

    const float4* src;
    if (row < G_ROWS) {
        int v  = row;
        int gl = v % GLEN; v /= GLEN;
        int h  = v % H;    v /= H;
        v >>= 7;                              // drop b
        int ld = v;                           // 0..11
        src = &g4[(((ld * GLEN + gl) * H + h) << 4) + c4h];
    } else {
        // HW wait for the primary grid's published d_idx (PDL semantics
        // guarantee visibility of pre-trigger writes after this call).
        cudaGridDependencySynchronize();
        int v  = row - G_ROWS;
        int m  = v % (TOPK * ELEN); v /= (TOPK * ELEN);
        int h  = v % H;             v /= H;
        int b  = v & 127;           v >>= 7;
        int ld = v;                           // 0..11
        int k  = m / ELEN;
        int e  = m - k * ELEN;
        int p  = __ldg(&d_idx[b * TOPK + k]);
        src = &pool4[((((p * 12 + ld) * ELEN + e) * H + h) << 4) + c4h];
    }

    float4 v0 = __ldg(src);
    float4 v1 = __ldg(src + 8);

    float4* dst = out4 + ((long long)row << 4) + c4h;
    __stcs(dst,     v0);
    __stcs(dst + 8, v1);
}

// ---------------------------------------------------------------------------
extern "C" void kernel_launch(void* const* d_in, const int* in_sizes, int n_in,
                              void* d_out, int out_size) {
    const float* query = (const float*)d_in[0];
    const float* gprm  = (const float*)d_in[1];
    const float* pool  = (const float*)d_in[2];
    const float* keys  = (const float*)d_in[3];
    float* out = (float*)d_out;

    // 1. top-k selection (PDL primary)
    select_topk_kernel<<<B, 512>>>((const float4*)query, (const float4*)keys);

    // 2. writer (PDL secondary): overlaps with selection; e-branch gated by
    //    the HW grid dependency.
    {
        cudaLaunchConfig_t cfg = {};
        cfg.gridDim  = dim3((TOTAL_PAIRS + 255) / 256);   // 60,480
        cfg.blockDim = dim3(256);
        cudaLaunchAttribute attr[1];
        attr[0].id = cudaLaunchAttributeProgrammaticStreamSerialization;
        attr[0].val.programmaticStreamSerializationAllowed = 1;
        cfg.attrs    = attr;
        cfg.numAttrs = 1;
        cudaLaunchKernelEx(&cfg, write_out_kernel,
                           (const float4*)gprm, (const float4*)pool,
                           (float4*)out);
    }
}